// round 12
// baseline (speedup 1.0000x reference)
#include <cuda_runtime.h>
#include <cuda_fp16.h>
#include <cstdint>
#include <math.h>

#define NN 100000
#define EE 1600000
#define ET 1700000      // edges + self loops
#define H 14
#define C 7
#define HC 98
#define CP 8            // padded channels (slot 7 carries alsrc fp16)
#define HCP 112         // H * CP
#define FIN 256
#define CAP 64          // bucket capacity per node (P(deg>63) ~ 1e-16)

// ---------------- scratch (device globals; reused across both layers) ----------
__device__ __align__(16) __half g_xh[NN * HCP]; // [N,H,8] fp16; ch7 = alsrc
__device__ float g_aldst[NN * H];    // per-node dst logits
__device__ float g_h[NN * C];        // layer-1 output features
__device__ int g_cnt[NN];            // in-degree (filled by scatter)
__device__ __align__(16) int g_bucket[NN * CAP]; // per-destination source lists

__device__ __forceinline__ float lrelu(float v) {
    return v > 0.0f ? v : 0.2f * v;
}

__device__ __forceinline__ unsigned int f2tf(float f) {
    unsigned int r;
    asm("cvt.rna.tf32.f32 %0, %1;" : "=r"(r) : "f"(f));
    return r;
}

__device__ __forceinline__ void mma_tf32(float* c, const unsigned int* a,
                                         unsigned int b0, unsigned int b1) {
    asm volatile(
        "mma.sync.aligned.m16n8k8.row.col.f32.tf32.tf32.f32 "
        "{%0,%1,%2,%3},{%4,%5,%6,%7},{%8,%9},{%0,%1,%2,%3};"
        : "+f"(c[0]), "+f"(c[1]), "+f"(c[2]), "+f"(c[3])
        : "r"(a[0]), "r"(a[1]), "r"(a[2]), "r"(a[3]), "r"(b0), "r"(b1));
}

// ---------------- bucket CSR build ---------------------------------------------
__global__ void k_zero() {
    const int i = blockIdx.x * blockDim.x + threadIdx.x;
    if (i < NN) g_cnt[i] = 0;
}

__global__ void k_scatter(const int* __restrict__ ei) {
    const int e = blockIdx.x * blockDim.x + threadIdx.x;
    if (e >= ET) return;
    int s, d;
    if (e < EE) { s = ei[e]; d = ei[EE + e]; } else { s = d = e - EE; }
    const int pos = atomicAdd(&g_cnt[d], 1);
    g_bucket[(d << 6) + pos] = s;
}

// ---------------- GEMM1 (TF32 MMA): x[N,256] @ W1[256,98] -> g_xh fp16 ---------
__global__ __launch_bounds__(256) void k_gemm1(const float* __restrict__ x,
                                               const float* __restrict__ W) {
    __shared__ float As[128][20];
    __shared__ float Bs[16][120];
    const int tid = threadIdx.x;
    const int warp = tid >> 5, lane = tid & 31;
    const int gid = lane >> 2, t4 = lane & 3;
    const int wm = warp >> 1, wn = warp & 1;
    const int bm = blockIdx.x * 128;
    const int rb0 = wm * 32;
    const int cb  = wn * 56;

    float acc[2][7][4];
#pragma unroll
    for (int mt = 0; mt < 2; mt++)
#pragma unroll
        for (int nt = 0; nt < 7; nt++)
#pragma unroll
            for (int q = 0; q < 4; q++) acc[mt][nt][q] = 0.0f;

    for (int k0 = 0; k0 < FIN; k0 += 16) {
#pragma unroll
        for (int i = 0; i < 2; i++) {
            const int idx = tid * 2 + i;
            const int row = idx >> 2, kq = idx & 3;
            float4 v = make_float4(0.f, 0.f, 0.f, 0.f);
            if (bm + row < NN) v = *(const float4*)&x[(size_t)(bm + row) * FIN + k0 + kq * 4];
            As[row][kq * 4 + 0] = v.x;
            As[row][kq * 4 + 1] = v.y;
            As[row][kq * 4 + 2] = v.z;
            As[row][kq * 4 + 3] = v.w;
        }
#pragma unroll
        for (int i = tid; i < 16 * HCP; i += 256) {
            const int k = i / HCP, cp = i % HCP;
            const int h = cp >> 3, c = cp & 7;
            Bs[k][cp] = (c < C) ? W[(size_t)(k0 + k) * HC + h * C + c] : 0.0f;
        }
        __syncthreads();
#pragma unroll
        for (int kk = 0; kk < 16; kk += 8) {
            unsigned int a[2][4];
#pragma unroll
            for (int mt = 0; mt < 2; mt++) {
                const int r = rb0 + mt * 16 + gid;
                a[mt][0] = f2tf(As[r][kk + t4]);
                a[mt][1] = f2tf(As[r + 8][kk + t4]);
                a[mt][2] = f2tf(As[r][kk + t4 + 4]);
                a[mt][3] = f2tf(As[r + 8][kk + t4 + 4]);
            }
#pragma unroll
            for (int nt = 0; nt < 7; nt++) {
                const unsigned int b0 = f2tf(Bs[kk + t4][cb + nt * 8 + gid]);
                const unsigned int b1 = f2tf(Bs[kk + t4 + 4][cb + nt * 8 + gid]);
#pragma unroll
                for (int mt = 0; mt < 2; mt++) mma_tf32(acc[mt][nt], a[mt], b0, b1);
            }
        }
        __syncthreads();
    }
#pragma unroll
    for (int mt = 0; mt < 2; mt++) {
        const int r0 = bm + rb0 + mt * 16 + gid;
#pragma unroll
        for (int nt = 0; nt < 7; nt++) {
            const int col = cb + nt * 8 + t4 * 2;
            if (r0 < NN)
                *(__half2*)&g_xh[(size_t)r0 * HCP + col] =
                    __floats2half2_rn(acc[mt][nt][0], acc[mt][nt][1]);
            if (r0 + 8 < NN)
                *(__half2*)&g_xh[(size_t)(r0 + 8) * HCP + col] =
                    __floats2half2_rn(acc[mt][nt][2], acc[mt][nt][3]);
        }
    }
}

// ---------------- attention logits: pack alsrc into xh pad slot ----------------
__global__ void k_al(const float* __restrict__ a_src, const float* __restrict__ a_dst) {
    const int i = blockIdx.x * blockDim.x + threadIdx.x;
    if (i >= NN * H) return;
    const int n = i / H, h = i % H;
    const uint4 u = *(const uint4*)&g_xh[(size_t)n * HCP + h * CP];
    const __half2* hp = (const __half2*)&u;
    float xv[8];
    float2 f;
    f = __half22float2(hp[0]); xv[0] = f.x; xv[1] = f.y;
    f = __half22float2(hp[1]); xv[2] = f.x; xv[3] = f.y;
    f = __half22float2(hp[2]); xv[4] = f.x; xv[5] = f.y;
    f = __half22float2(hp[3]); xv[6] = f.x;
    float s1 = 0.0f, s2 = 0.0f;
#pragma unroll
    for (int c = 0; c < C; c++) {
        s1 = fmaf(xv[c], a_src[h * C + c], s1);
        s2 = fmaf(xv[c], a_dst[h * C + c], s2);
    }
    g_aldst[i] = s2;
    g_xh[(size_t)n * HCP + h * CP + 7] = __float2half_rn(s1);  // pack alsrc
}

// ---------------- fused node pass: softmax + max agg + head reduce -------------
// 32 nodes/block, 14 threads/node; half2 weight path (exp for 2 edges per MUFU).
template<int MODE>
__global__ __launch_bounds__(448, 3) void k_node(const float* __restrict__ b,
                                                 float* __restrict__ out) {
    __shared__ float sm[32][H][CP];          // 14 KB
    const int tid = threadIdx.x;             // 448 = 32 nodes * 14 heads
    const int ln = tid / H;
    const int h  = tid % H;
    const int n  = blockIdx.x * 32 + ln;

    if (n < NN) {
        const int cnt = g_cnt[n];
        const int base = n << 6;
        const float ad = g_aldst[n * H + h];
        const __half2 ad2 = __float2half2_rn(ad);
        const __half2 SLOPE = __float2half2_rn(0.2f);
        float den = 0.0f;
        const __half2 NEG2 = __float2half2_rn(-INFINITY);
        __half2 ah0 = NEG2, ah1 = NEG2, ah2 = NEG2, ah3 = NEG2;

        // ---- full chunks of 4 (no per-edge guards) ----
        int j0 = 0;
        for (; j0 + 4 <= cnt; j0 += 4) {
            const int4 q = *(const int4*)&g_bucket[base + j0];
            const uint4 u0 = *(const uint4*)&g_xh[(size_t)q.x * HCP + h * CP];
            const uint4 u1 = *(const uint4*)&g_xh[(size_t)q.y * HCP + h * CP];
            const uint4 u2 = *(const uint4*)&g_xh[(size_t)q.z * HCP + h * CP];
            const uint4 u3 = *(const uint4*)&g_xh[(size_t)q.w * HCP + h * CP];
            const __half2* p0 = (const __half2*)&u0;
            const __half2* p1 = (const __half2*)&u1;
            const __half2* p2 = (const __half2*)&u2;
            const __half2* p3 = (const __half2*)&u3;

            // weight path in half2: 2 edges per exp
            const __half2 alsA = __halves2half2(__high2half(p0[3]), __high2half(p1[3]));
            const __half2 alsB = __halves2half2(__high2half(p2[3]), __high2half(p3[3]));
            const __half2 lA = __hadd2(alsA, ad2);
            const __half2 lB = __hadd2(alsB, ad2);
            const __half2 rA = __hmax2(lA, __hmul2(lA, SLOPE));   // leaky relu
            const __half2 rB = __hmax2(lB, __hmul2(lB, SLOPE));
            const __half2 wA = h2exp(rA);
            const __half2 wB = h2exp(rB);
            const float2 ws = __half22float2(__hadd2(wA, wB));    // pairwise den
            den += ws.x + ws.y;
            const __half2 w0 = __low2half2(wA);
            const __half2 w1 = __high2half2(wA);
            const __half2 w2 = __low2half2(wB);
            const __half2 w3 = __high2half2(wB);

            ah0 = __hmax2(ah0, __hmul2(w0, p0[0]));
            ah1 = __hmax2(ah1, __hmul2(w0, p0[1]));
            ah2 = __hmax2(ah2, __hmul2(w0, p0[2]));
            ah3 = __hmax2(ah3, __hmul2(w0, p0[3]));
            ah0 = __hmax2(ah0, __hmul2(w1, p1[0]));
            ah1 = __hmax2(ah1, __hmul2(w1, p1[1]));
            ah2 = __hmax2(ah2, __hmul2(w1, p1[2]));
            ah3 = __hmax2(ah3, __hmul2(w1, p1[3]));
            ah0 = __hmax2(ah0, __hmul2(w2, p2[0]));
            ah1 = __hmax2(ah1, __hmul2(w2, p2[1]));
            ah2 = __hmax2(ah2, __hmul2(w2, p2[2]));
            ah3 = __hmax2(ah3, __hmul2(w2, p2[3]));
            ah0 = __hmax2(ah0, __hmul2(w3, p3[0]));
            ah1 = __hmax2(ah1, __hmul2(w3, p3[1]));
            ah2 = __hmax2(ah2, __hmul2(w3, p3[2]));
            ah3 = __hmax2(ah3, __hmul2(w3, p3[3]));
        }
        // ---- scalar tail (<= 3 edges) ----
        for (; j0 < cnt; j0++) {
            const int s = g_bucket[base + j0];
            const uint4 u = *(const uint4*)&g_xh[(size_t)s * HCP + h * CP];
            const __half2* hp = (const __half2*)&u;
            const float als = __half2float(__high2half(hp[3]));
            const float l = lrelu(als + ad);
            const float w = __expf(l);
            den += w;
            const __half2 w2 = __float2half2_rn(w);
            ah0 = __hmax2(ah0, __hmul2(w2, hp[0]));
            ah1 = __hmax2(ah1, __hmul2(w2, hp[1]));
            ah2 = __hmax2(ah2, __hmul2(w2, hp[2]));
            ah3 = __hmax2(ah3, __hmul2(w2, hp[3]));
        }

        const float inv = 1.0f / den;        // den > 0 (self loop => deg >= 1)
        const float2 F0 = __half22float2(ah0);
        const float2 F1 = __half22float2(ah1);
        const float2 F2 = __half22float2(ah2);
        const float2 F3 = __half22float2(ah3);
        sm[ln][h][0] = F0.x * inv;
        sm[ln][h][1] = F0.y * inv;
        sm[ln][h][2] = F1.x * inv;
        sm[ln][h][3] = F1.y * inv;
        sm[ln][h][4] = F2.x * inv;
        sm[ln][h][5] = F2.y * inv;
        sm[ln][h][6] = F3.x * inv;
    }
    __syncthreads();

    if (MODE == 0) {
        if (tid < 32 * C) {
            const int l2 = tid / C, c = tid % C;
            const int nn = blockIdx.x * 32 + l2;
            if (nn < NN) {
                float s = 0.0f;
#pragma unroll
                for (int hh = 0; hh < H; hh++) s += sm[l2][hh][c];
                out[nn * C + c] = fmaxf(s * (1.0f / H) + b[c], 0.0f);
            }
        }
    } else {
        if (tid < 32) {
            const int nn = blockIdx.x * 32 + tid;
            if (nn < NN) {
                float v[C];
#pragma unroll
                for (int c = 0; c < C; c++) {
                    float s = 0.0f;
#pragma unroll
                    for (int hh = 0; hh < H; hh++) s += sm[tid][hh][c];
                    v[c] = s * (1.0f / H) + b[c];
                }
                float mx = v[0];
#pragma unroll
                for (int c = 1; c < C; c++) mx = fmaxf(mx, v[c]);
                float se = 0.0f;
#pragma unroll
                for (int c = 0; c < C; c++) se += __expf(v[c] - mx);
                const float lse = mx + logf(se);
#pragma unroll
                for (int c = 0; c < C; c++) out[nn * C + c] = v[c] - lse;
            }
        }
    }
}

// ---------------- fused GEMM2 + attention logits (layer 2) ---------------------
__global__ __launch_bounds__(256) void k_gemm2al(const float* __restrict__ W2,
                                                 const float* __restrict__ a_src,
                                                 const float* __restrict__ a_dst) {
    __shared__ float W2s[C][HC];   // 7 x 98
    __shared__ float As[HC], Ad[HC];
    const int tid = threadIdx.x;
    for (int i = tid; i < C * HC; i += 256) W2s[i / HC][i % HC] = W2[i];
    for (int i = tid; i < HC; i += 256) { As[i] = a_src[i]; Ad[i] = a_dst[i]; }
    __syncthreads();

    const int i = blockIdx.x * 256 + tid;
    if (i >= NN * H) return;
    const int n = i / H, h = i % H;
    float hv[C];
#pragma unroll
    for (int k = 0; k < C; k++) hv[k] = g_h[n * C + k];
    float o[C];
    float s1 = 0.0f, s2 = 0.0f;
#pragma unroll
    for (int c = 0; c < C; c++) {
        float s = 0.0f;
#pragma unroll
        for (int k = 0; k < C; k++) s = fmaf(hv[k], W2s[k][h * C + c], s);
        o[c] = s;
        s1 = fmaf(s, As[h * C + c], s1);
        s2 = fmaf(s, Ad[h * C + c], s2);
    }
    g_aldst[i] = s2;
    uint4 u;
    __half2* hp = (__half2*)&u;
    hp[0] = __floats2half2_rn(o[0], o[1]);
    hp[1] = __floats2half2_rn(o[2], o[3]);
    hp[2] = __floats2half2_rn(o[4], o[5]);
    hp[3] = __floats2half2_rn(o[6], s1);   // pack alsrc into pad slot
    *(uint4*)&g_xh[(size_t)n * HCP + h * CP] = u;
}

extern "C" void kernel_launch(void* const* d_in, const int* in_sizes, int n_in,
                              void* d_out, int out_size) {
    const float* x      = (const float*)d_in[0];
    const int*   ei     = (const int*)  d_in[1];
    const float* W1     = (const float*)d_in[2];
    const float* a_src1 = (const float*)d_in[3];
    const float* a_dst1 = (const float*)d_in[4];
    const float* b1     = (const float*)d_in[5];
    const float* W2     = (const float*)d_in[6];
    const float* a_src2 = (const float*)d_in[7];
    const float* a_dst2 = (const float*)d_in[8];
    const float* b2     = (const float*)d_in[9];
    float* out = (float*)d_out;

    const int EB = (ET + 255) / 256;
    const int NB = (NN + 31) / 32;

    float* g_h_ptr;
    cudaGetSymbolAddress((void**)&g_h_ptr, g_h);

    // ----- bucket CSR (shared by both layers) -----
    k_zero   <<<(NN + 255) / 256, 256>>>();
    k_scatter<<<EB, 256>>>(ei);

    // ----- layer 1 -----
    k_gemm1  <<<(NN + 127) / 128, 256>>>(x, W1);
    k_al     <<<(NN * H + 255) / 256, 256>>>(a_src1, a_dst1);
    k_node<0><<<NB, 448>>>(b1, g_h_ptr);

    // ----- layer 2 -----
    k_gemm2al<<<(NN * H + 255) / 256, 256>>>(W2, a_src2, a_dst2);
    k_node<1><<<NB, 448>>>(b2, out);
}

// round 13
// speedup vs baseline: 1.0206x; 1.0206x over previous
#include <cuda_runtime.h>
#include <cuda_fp16.h>
#include <cstdint>
#include <math.h>

#define NN 100000
#define EE 1600000
#define ET 1700000      // edges + self loops
#define H 14
#define C 7
#define HC 98
#define CP 8            // padded channels (slot 7 carries alsrc fp16)
#define HCP 112         // H * CP
#define FIN 256
#define BN 128          // GEMM1 N: 112 packed xh + 14 aldst + 2 unused
#define CAP 64          // bucket capacity per node (P(deg>63) ~ 1e-16)

// ---------------- scratch (device globals; reused across both layers) ----------
__device__ __align__(16) __half g_xh[NN * HCP]; // [N,H,8] fp16; ch7 = alsrc
__device__ float g_aldst[NN * H];    // per-node dst logits
__device__ float g_h[NN * C];        // layer-1 output features
__device__ int g_cnt[NN];            // in-degree (filled by scatter)
__device__ __align__(16) int g_bucket[NN * CAP]; // per-destination source lists
__device__ __align__(16) float g_Bext[FIN * BN]; // extended GEMM1 B matrix

__device__ __forceinline__ float lrelu(float v) {
    return v > 0.0f ? v : 0.2f * v;
}

__device__ __forceinline__ unsigned int f2tf(float f) {
    unsigned int r;
    asm("cvt.rna.tf32.f32 %0, %1;" : "=r"(r) : "f"(f));
    return r;
}

__device__ __forceinline__ void mma_tf32(float* c, const unsigned int* a,
                                         unsigned int b0, unsigned int b1) {
    asm volatile(
        "mma.sync.aligned.m16n8k8.row.col.f32.tf32.tf32.f32 "
        "{%0,%1,%2,%3},{%4,%5,%6,%7},{%8,%9},{%0,%1,%2,%3};"
        : "+f"(c[0]), "+f"(c[1]), "+f"(c[2]), "+f"(c[3])
        : "r"(a[0]), "r"(a[1]), "r"(a[2]), "r"(a[3]), "r"(b0), "r"(b1));
}

// ---------------- bucket CSR build ---------------------------------------------
__global__ void k_zero() {
    const int i = blockIdx.x * blockDim.x + threadIdx.x;
    if (i < NN) g_cnt[i] = 0;
}

__global__ void k_scatter(const int* __restrict__ ei) {
    const int e = blockIdx.x * blockDim.x + threadIdx.x;
    if (e >= ET) return;
    int s, d;
    if (e < EE) { s = ei[e]; d = ei[EE + e]; } else { s = d = e - EE; }
    const int pos = atomicAdd(&g_cnt[d], 1);
    g_bucket[(d << 6) + pos] = s;
}

// ---------------- build extended B: xh cols + alsrc col + aldst cols -----------
__global__ void k_prep(const float* __restrict__ W1,
                       const float* __restrict__ a_src,
                       const float* __restrict__ a_dst) {
    const int i = blockIdx.x * blockDim.x + threadIdx.x;  // k*BN + col
    if (i >= FIN * BN) return;
    const int k = i / BN, col = i % BN;
    float v = 0.0f;
    if (col < HCP) {
        const int h = col >> 3, c = col & 7;
        if (c < C) {
            v = W1[k * HC + h * C + c];
        } else {  // alsrc column for head h
            float s = 0.0f;
#pragma unroll
            for (int cc = 0; cc < C; cc++)
                s = fmaf(W1[k * HC + h * C + cc], a_src[h * C + cc], s);
            v = s;
        }
    } else if (col < HCP + H) {  // aldst column for head col-112
        const int h = col - HCP;
        float s = 0.0f;
#pragma unroll
        for (int cc = 0; cc < C; cc++)
            s = fmaf(W1[k * HC + h * C + cc], a_dst[h * C + cc], s);
        v = s;
    }
    g_Bext[i] = v;
}

// ---------------- GEMM1 (TF32 MMA): x[N,256] @ Bext[256,128] -------------------
// cols 0..111 -> g_xh fp16 packed (alsrc in ch7); cols 112..125 -> g_aldst fp32
__global__ __launch_bounds__(256) void k_gemm1(const float* __restrict__ x) {
    __shared__ float As[128][20];
    __shared__ float Bs[16][136];   // stride 136 (==8 mod 32): conflict-free frags
    const int tid = threadIdx.x;
    const int warp = tid >> 5, lane = tid & 31;
    const int gid = lane >> 2, t4 = lane & 3;
    const int wm = warp >> 1, wn = warp & 1;
    const int bm = blockIdx.x * 128;
    const int rb0 = wm * 32;
    const int cb  = wn * 64;

    float acc[2][8][4];
#pragma unroll
    for (int mt = 0; mt < 2; mt++)
#pragma unroll
        for (int nt = 0; nt < 8; nt++)
#pragma unroll
            for (int q = 0; q < 4; q++) acc[mt][nt][q] = 0.0f;

    for (int k0 = 0; k0 < FIN; k0 += 16) {
        // load A tile 128x16
#pragma unroll
        for (int i = 0; i < 2; i++) {
            const int idx = tid * 2 + i;
            const int row = idx >> 2, kq = idx & 3;
            float4 v = make_float4(0.f, 0.f, 0.f, 0.f);
            if (bm + row < NN) v = *(const float4*)&x[(size_t)(bm + row) * FIN + k0 + kq * 4];
            As[row][kq * 4 + 0] = v.x;
            As[row][kq * 4 + 1] = v.y;
            As[row][kq * 4 + 2] = v.z;
            As[row][kq * 4 + 3] = v.w;
        }
        // load B tile 16x128 (coalesced float4, branch-free)
#pragma unroll
        for (int i = 0; i < 2; i++) {
            const int idx = tid * 2 + i;          // 0..511
            const int row = idx >> 5, c4 = idx & 31;
            const float4 v = *(const float4*)&g_Bext[(k0 + row) * BN + c4 * 4];
            Bs[row][c4 * 4 + 0] = v.x;
            Bs[row][c4 * 4 + 1] = v.y;
            Bs[row][c4 * 4 + 2] = v.z;
            Bs[row][c4 * 4 + 3] = v.w;
        }
        __syncthreads();
#pragma unroll
        for (int kk = 0; kk < 16; kk += 8) {
            unsigned int a[2][4];
#pragma unroll
            for (int mt = 0; mt < 2; mt++) {
                const int r = rb0 + mt * 16 + gid;
                a[mt][0] = f2tf(As[r][kk + t4]);
                a[mt][1] = f2tf(As[r + 8][kk + t4]);
                a[mt][2] = f2tf(As[r][kk + t4 + 4]);
                a[mt][3] = f2tf(As[r + 8][kk + t4 + 4]);
            }
#pragma unroll
            for (int nt = 0; nt < 8; nt++) {
                const unsigned int b0 = f2tf(Bs[kk + t4][cb + nt * 8 + gid]);
                const unsigned int b1 = f2tf(Bs[kk + t4 + 4][cb + nt * 8 + gid]);
#pragma unroll
                for (int mt = 0; mt < 2; mt++) mma_tf32(acc[mt][nt], a[mt], b0, b1);
            }
        }
        __syncthreads();
    }
    // epilogue: packed fp16 store (cols<112) or fp32 aldst store (cols 112..125)
#pragma unroll
    for (int mt = 0; mt < 2; mt++) {
        const int r0 = bm + rb0 + mt * 16 + gid;
        const int r1 = r0 + 8;
#pragma unroll
        for (int nt = 0; nt < 8; nt++) {
            const int col = cb + nt * 8 + t4 * 2;
            if (col < HCP) {
                if (r0 < NN)
                    *(__half2*)&g_xh[(size_t)r0 * HCP + col] =
                        __floats2half2_rn(acc[mt][nt][0], acc[mt][nt][1]);
                if (r1 < NN)
                    *(__half2*)&g_xh[(size_t)r1 * HCP + col] =
                        __floats2half2_rn(acc[mt][nt][2], acc[mt][nt][3]);
            } else {
                const int h0 = col - HCP, h1 = h0 + 1;
                if (r0 < NN) {
                    if (h0 < H) g_aldst[r0 * H + h0] = acc[mt][nt][0];
                    if (h1 < H) g_aldst[r0 * H + h1] = acc[mt][nt][1];
                }
                if (r1 < NN) {
                    if (h0 < H) g_aldst[r1 * H + h0] = acc[mt][nt][2];
                    if (h1 < H) g_aldst[r1 * H + h1] = acc[mt][nt][3];
                }
            }
        }
    }
}

// ---------------- fused node pass: softmax + max agg + head reduce -------------
// 32 nodes/block, 14 threads/node; chunk-of-4 loads; scalar weight path.
template<int MODE>
__global__ __launch_bounds__(448, 3) void k_node(const float* __restrict__ b,
                                                 float* __restrict__ out) {
    __shared__ float sm[32][H][CP];          // 14 KB
    const int tid = threadIdx.x;             // 448 = 32 nodes * 14 heads
    const int ln = tid / H;
    const int h  = tid % H;
    const int n  = blockIdx.x * 32 + ln;

    if (n < NN) {
        const int cnt = g_cnt[n];
        const int base = n << 6;
        const float ad = g_aldst[n * H + h];
        float den = 0.0f;
        const __half2 NEG2 = __float2half2_rn(-INFINITY);
        __half2 ah0 = NEG2, ah1 = NEG2, ah2 = NEG2, ah3 = NEG2;

        for (int j0 = 0; j0 < cnt; j0 += 4) {
            const int4 q = *(const int4*)&g_bucket[base + j0];
            const int m = cnt - j0;
            int ss[4] = {q.x, q.y, q.z, q.w};
            uint4 u[4];
#pragma unroll
            for (int k = 0; k < 4; k++)
                if (k < m) u[k] = *(const uint4*)&g_xh[(size_t)ss[k] * HCP + h * CP];
#pragma unroll
            for (int k = 0; k < 4; k++) {
                if (k < m) {
                    const __half2* hp = (const __half2*)&u[k];
                    const float als = __half2float(__high2half(hp[3]));
                    const float l = lrelu(als + ad);
                    const float w = __expf(l);
                    den += w;
                    const __half2 w2 = __float2half2_rn(w);
                    ah0 = __hmax2(ah0, __hmul2(w2, hp[0]));
                    ah1 = __hmax2(ah1, __hmul2(w2, hp[1]));
                    ah2 = __hmax2(ah2, __hmul2(w2, hp[2]));
                    ah3 = __hmax2(ah3, __hmul2(w2, hp[3]));  // .y garbage, discarded
                }
            }
        }
        const float inv = 1.0f / den;        // den > 0 (self loop => deg >= 1)
        const float2 F0 = __half22float2(ah0);
        const float2 F1 = __half22float2(ah1);
        const float2 F2 = __half22float2(ah2);
        const float2 F3 = __half22float2(ah3);
        sm[ln][h][0] = F0.x * inv;
        sm[ln][h][1] = F0.y * inv;
        sm[ln][h][2] = F1.x * inv;
        sm[ln][h][3] = F1.y * inv;
        sm[ln][h][4] = F2.x * inv;
        sm[ln][h][5] = F2.y * inv;
        sm[ln][h][6] = F3.x * inv;
    }
    __syncthreads();

    if (MODE == 0) {
        if (tid < 32 * C) {
            const int l2 = tid / C, c = tid % C;
            const int nn = blockIdx.x * 32 + l2;
            if (nn < NN) {
                float s = 0.0f;
#pragma unroll
                for (int hh = 0; hh < H; hh++) s += sm[l2][hh][c];
                out[nn * C + c] = fmaxf(s * (1.0f / H) + b[c], 0.0f);
            }
        }
    } else {
        if (tid < 32) {
            const int nn = blockIdx.x * 32 + tid;
            if (nn < NN) {
                float v[C];
#pragma unroll
                for (int c = 0; c < C; c++) {
                    float s = 0.0f;
#pragma unroll
                    for (int hh = 0; hh < H; hh++) s += sm[tid][hh][c];
                    v[c] = s * (1.0f / H) + b[c];
                }
                float mx = v[0];
#pragma unroll
                for (int c = 1; c < C; c++) mx = fmaxf(mx, v[c]);
                float se = 0.0f;
#pragma unroll
                for (int c = 0; c < C; c++) se += __expf(v[c] - mx);
                const float lse = mx + logf(se);
#pragma unroll
                for (int c = 0; c < C; c++) out[nn * C + c] = v[c] - lse;
            }
        }
    }
}

// ---------------- fused GEMM2 + attention logits (layer 2) ---------------------
__global__ __launch_bounds__(256) void k_gemm2al(const float* __restrict__ W2,
                                                 const float* __restrict__ a_src,
                                                 const float* __restrict__ a_dst) {
    __shared__ float W2s[C][HC];   // 7 x 98
    __shared__ float As[HC], Ad[HC];
    const int tid = threadIdx.x;
    for (int i = tid; i < C * HC; i += 256) W2s[i / HC][i % HC] = W2[i];
    for (int i = tid; i < HC; i += 256) { As[i] = a_src[i]; Ad[i] = a_dst[i]; }
    __syncthreads();

    const int i = blockIdx.x * 256 + tid;
    if (i >= NN * H) return;
    const int n = i / H, h = i % H;
    float hv[C];
#pragma unroll
    for (int k = 0; k < C; k++) hv[k] = g_h[n * C + k];
    float o[C];
    float s1 = 0.0f, s2 = 0.0f;
#pragma unroll
    for (int c = 0; c < C; c++) {
        float s = 0.0f;
#pragma unroll
        for (int k = 0; k < C; k++) s = fmaf(hv[k], W2s[k][h * C + c], s);
        o[c] = s;
        s1 = fmaf(s, As[h * C + c], s1);
        s2 = fmaf(s, Ad[h * C + c], s2);
    }
    g_aldst[i] = s2;
    uint4 u;
    __half2* hp = (__half2*)&u;
    hp[0] = __floats2half2_rn(o[0], o[1]);
    hp[1] = __floats2half2_rn(o[2], o[3]);
    hp[2] = __floats2half2_rn(o[4], o[5]);
    hp[3] = __floats2half2_rn(o[6], s1);   // pack alsrc into pad slot
    *(uint4*)&g_xh[(size_t)n * HCP + h * CP] = u;
}

extern "C" void kernel_launch(void* const* d_in, const int* in_sizes, int n_in,
                              void* d_out, int out_size) {
    const float* x      = (const float*)d_in[0];
    const int*   ei     = (const int*)  d_in[1];
    const float* W1     = (const float*)d_in[2];
    const float* a_src1 = (const float*)d_in[3];
    const float* a_dst1 = (const float*)d_in[4];
    const float* b1     = (const float*)d_in[5];
    const float* W2     = (const float*)d_in[6];
    const float* a_src2 = (const float*)d_in[7];
    const float* a_dst2 = (const float*)d_in[8];
    const float* b2     = (const float*)d_in[9];
    float* out = (float*)d_out;

    const int EB = (ET + 255) / 256;
    const int NB = (NN + 31) / 32;

    float* g_h_ptr;
    cudaGetSymbolAddress((void**)&g_h_ptr, g_h);

    // ----- prep + bucket CSR -----
    k_prep   <<<(FIN * BN + 255) / 256, 256>>>(W1, a_src1, a_dst1);
    k_zero   <<<(NN + 255) / 256, 256>>>();
    k_scatter<<<EB, 256>>>(ei);

    // ----- layer 1 -----
    k_gemm1  <<<(NN + 127) / 128, 256>>>(x);
    k_node<0><<<NB, 448>>>(b1, g_h_ptr);

    // ----- layer 2 -----
    k_gemm2al<<<(NN * H + 255) / 256, 256>>>(W2, a_src2, a_dst2);
    k_node<1><<<NB, 448>>>(b2, out);
}

// round 14
// speedup vs baseline: 1.0564x; 1.0351x over previous
#include <cuda_runtime.h>
#include <cuda_fp16.h>
#include <cstdint>
#include <math.h>

#define NN 100000
#define EE 1600000
#define ET 1700000      // edges + self loops
#define H 14
#define C 7
#define HC 98
#define CP 8            // padded channels (slot 7 carries alsrc fp16)
#define HCP 112         // H * CP
#define FIN 256
#define BN 128          // GEMM1 N: 112 packed xh + 14 aldst + 2 unused
#define CAP 64          // bucket capacity per node (P(deg>63) ~ 1e-16)

// ---------------- scratch (device globals; reused across both layers) ----------
__device__ __align__(16) __half g_xh[NN * HCP]; // [N,H,8] fp16; ch7 = alsrc
__device__ float g_aldst[NN * H];    // per-node dst logits
__device__ float g_h[NN * C];        // layer-1 output features
__device__ int g_cnt[NN];            // in-degree (filled by scatter)
__device__ __align__(16) int g_bucket[NN * CAP]; // per-destination source lists
__device__ __align__(16) float g_Bext[FIN * BN]; // extended GEMM1 B matrix

__device__ __forceinline__ float lrelu(float v) {
    return v > 0.0f ? v : 0.2f * v;
}

__device__ __forceinline__ unsigned int f2tf(float f) {
    unsigned int r;
    asm("cvt.rna.tf32.f32 %0, %1;" : "=r"(r) : "f"(f));
    return r;
}

__device__ __forceinline__ void mma_tf32(float* c, const unsigned int* a,
                                         unsigned int b0, unsigned int b1) {
    asm volatile(
        "mma.sync.aligned.m16n8k8.row.col.f32.tf32.tf32.f32 "
        "{%0,%1,%2,%3},{%4,%5,%6,%7},{%8,%9},{%0,%1,%2,%3};"
        : "+f"(c[0]), "+f"(c[1]), "+f"(c[2]), "+f"(c[3])
        : "r"(a[0]), "r"(a[1]), "r"(a[2]), "r"(a[3]), "r"(b0), "r"(b1));
}

// ---------------- bucket CSR build ---------------------------------------------
__global__ void k_zero() {
    const int i = blockIdx.x * blockDim.x + threadIdx.x;
    if (i < NN) g_cnt[i] = 0;
}

__global__ void k_scatter(const int* __restrict__ ei) {
    const int e = blockIdx.x * blockDim.x + threadIdx.x;
    if (e >= ET) return;
    int s, d;
    if (e < EE) { s = ei[e]; d = ei[EE + e]; } else { s = d = e - EE; }
    const int pos = atomicAdd(&g_cnt[d], 1);
    g_bucket[(d << 6) + pos] = s;
}

// ---------------- build extended B: xh cols + alsrc col + aldst cols -----------
__global__ void k_prep(const float* __restrict__ W1,
                       const float* __restrict__ a_src,
                       const float* __restrict__ a_dst) {
    const int i = blockIdx.x * blockDim.x + threadIdx.x;  // k*BN + col
    if (i >= FIN * BN) return;
    const int k = i / BN, col = i % BN;
    float v = 0.0f;
    if (col < HCP) {
        const int h = col >> 3, c = col & 7;
        if (c < C) {
            v = W1[k * HC + h * C + c];
        } else {  // alsrc column for head h
            float s = 0.0f;
#pragma unroll
            for (int cc = 0; cc < C; cc++)
                s = fmaf(W1[k * HC + h * C + cc], a_src[h * C + cc], s);
            v = s;
        }
    } else if (col < HCP + H) {  // aldst column for head col-112
        const int h = col - HCP;
        float s = 0.0f;
#pragma unroll
        for (int cc = 0; cc < C; cc++)
            s = fmaf(W1[k * HC + h * C + cc], a_dst[h * C + cc], s);
        v = s;
    }
    g_Bext[i] = v;
}

// ---------------- GEMM1 (TF32 MMA, double-buffered): x @ Bext[256,128] ---------
// cols 0..111 -> g_xh fp16 packed (alsrc in ch7); cols 112..125 -> g_aldst fp32
__global__ __launch_bounds__(256) void k_gemm1(const float* __restrict__ x) {
    __shared__ unsigned int As[2][128][20];   // tf32 bits, stride 20
    __shared__ unsigned int Bs[2][16][136];   // tf32 bits, stride 136
    const int tid = threadIdx.x;
    const int warp = tid >> 5, lane = tid & 31;
    const int gid = lane >> 2, t4 = lane & 3;
    const int wm = warp >> 1, wn = warp & 1;
    const int bm = blockIdx.x * 128;
    const int rb0 = wm * 32;
    const int cb  = wn * 64;

    // cooperative-load addressing (2 float4 per thread for each of A and B)
    const int idx0 = tid * 2, idx1 = tid * 2 + 1;
    const int arow0 = idx0 >> 2, akq0 = idx0 & 3;
    const int arow1 = idx1 >> 2, akq1 = idx1 & 3;
    const int brow0 = idx0 >> 5, bc40 = idx0 & 31;
    const int brow1 = idx1 >> 5, bc41 = idx1 & 31;
    const bool aok0 = (bm + arow0 < NN);
    const bool aok1 = (bm + arow1 < NN);

    float acc[2][8][4];
#pragma unroll
    for (int mt = 0; mt < 2; mt++)
#pragma unroll
        for (int nt = 0; nt < 8; nt++)
#pragma unroll
            for (int q = 0; q < 4; q++) acc[mt][nt][q] = 0.0f;

    const float4 Z4 = make_float4(0.f, 0.f, 0.f, 0.f);
    float4 pa0, pa1, pb0, pb1;

    // prologue: load tile 0 into registers, store to buffer 0
    pa0 = aok0 ? *(const float4*)&x[(size_t)(bm + arow0) * FIN + akq0 * 4] : Z4;
    pa1 = aok1 ? *(const float4*)&x[(size_t)(bm + arow1) * FIN + akq1 * 4] : Z4;
    pb0 = *(const float4*)&g_Bext[brow0 * BN + bc40 * 4];
    pb1 = *(const float4*)&g_Bext[brow1 * BN + bc41 * 4];
    As[0][arow0][akq0 * 4 + 0] = f2tf(pa0.x);
    As[0][arow0][akq0 * 4 + 1] = f2tf(pa0.y);
    As[0][arow0][akq0 * 4 + 2] = f2tf(pa0.z);
    As[0][arow0][akq0 * 4 + 3] = f2tf(pa0.w);
    As[0][arow1][akq1 * 4 + 0] = f2tf(pa1.x);
    As[0][arow1][akq1 * 4 + 1] = f2tf(pa1.y);
    As[0][arow1][akq1 * 4 + 2] = f2tf(pa1.z);
    As[0][arow1][akq1 * 4 + 3] = f2tf(pa1.w);
    Bs[0][brow0][bc40 * 4 + 0] = f2tf(pb0.x);
    Bs[0][brow0][bc40 * 4 + 1] = f2tf(pb0.y);
    Bs[0][brow0][bc40 * 4 + 2] = f2tf(pb0.z);
    Bs[0][brow0][bc40 * 4 + 3] = f2tf(pb0.w);
    Bs[0][brow1][bc41 * 4 + 0] = f2tf(pb1.x);
    Bs[0][brow1][bc41 * 4 + 1] = f2tf(pb1.y);
    Bs[0][brow1][bc41 * 4 + 2] = f2tf(pb1.z);
    Bs[0][brow1][bc41 * 4 + 3] = f2tf(pb1.w);
    __syncthreads();

#pragma unroll 1
    for (int t = 0; t < 16; t++) {
        const int buf = t & 1;
        // prefetch next tile into registers (overlaps with MMA below)
        if (t < 15) {
            const int k0 = (t + 1) * 16;
            pa0 = aok0 ? *(const float4*)&x[(size_t)(bm + arow0) * FIN + k0 + akq0 * 4] : Z4;
            pa1 = aok1 ? *(const float4*)&x[(size_t)(bm + arow1) * FIN + k0 + akq1 * 4] : Z4;
            pb0 = *(const float4*)&g_Bext[(k0 + brow0) * BN + bc40 * 4];
            pb1 = *(const float4*)&g_Bext[(k0 + brow1) * BN + bc41 * 4];
        }
        // MMAs on current buffer (no cvt in this loop)
#pragma unroll
        for (int kk = 0; kk < 16; kk += 8) {
            unsigned int a[2][4];
#pragma unroll
            for (int mt = 0; mt < 2; mt++) {
                const int r = rb0 + mt * 16 + gid;
                a[mt][0] = As[buf][r][kk + t4];
                a[mt][1] = As[buf][r + 8][kk + t4];
                a[mt][2] = As[buf][r][kk + t4 + 4];
                a[mt][3] = As[buf][r + 8][kk + t4 + 4];
            }
#pragma unroll
            for (int nt = 0; nt < 8; nt++) {
                const unsigned int b0 = Bs[buf][kk + t4][cb + nt * 8 + gid];
                const unsigned int b1 = Bs[buf][kk + t4 + 4][cb + nt * 8 + gid];
#pragma unroll
                for (int mt = 0; mt < 2; mt++) mma_tf32(acc[mt][nt], a[mt], b0, b1);
            }
        }
        // store prefetched tile into the other buffer
        if (t < 15) {
            const int nb = buf ^ 1;
            As[nb][arow0][akq0 * 4 + 0] = f2tf(pa0.x);
            As[nb][arow0][akq0 * 4 + 1] = f2tf(pa0.y);
            As[nb][arow0][akq0 * 4 + 2] = f2tf(pa0.z);
            As[nb][arow0][akq0 * 4 + 3] = f2tf(pa0.w);
            As[nb][arow1][akq1 * 4 + 0] = f2tf(pa1.x);
            As[nb][arow1][akq1 * 4 + 1] = f2tf(pa1.y);
            As[nb][arow1][akq1 * 4 + 2] = f2tf(pa1.z);
            As[nb][arow1][akq1 * 4 + 3] = f2tf(pa1.w);
            Bs[nb][brow0][bc40 * 4 + 0] = f2tf(pb0.x);
            Bs[nb][brow0][bc40 * 4 + 1] = f2tf(pb0.y);
            Bs[nb][brow0][bc40 * 4 + 2] = f2tf(pb0.z);
            Bs[nb][brow0][bc40 * 4 + 3] = f2tf(pb0.w);
            Bs[nb][brow1][bc41 * 4 + 0] = f2tf(pb1.x);
            Bs[nb][brow1][bc41 * 4 + 1] = f2tf(pb1.y);
            Bs[nb][brow1][bc41 * 4 + 2] = f2tf(pb1.z);
            Bs[nb][brow1][bc41 * 4 + 3] = f2tf(pb1.w);
        }
        __syncthreads();
    }

    // epilogue: packed fp16 store (cols<112) or fp32 aldst store (cols 112..125)
#pragma unroll
    for (int mt = 0; mt < 2; mt++) {
        const int r0 = bm + rb0 + mt * 16 + gid;
        const int r1 = r0 + 8;
#pragma unroll
        for (int nt = 0; nt < 8; nt++) {
            const int col = cb + nt * 8 + t4 * 2;
            if (col < HCP) {
                if (r0 < NN)
                    *(__half2*)&g_xh[(size_t)r0 * HCP + col] =
                        __floats2half2_rn(acc[mt][nt][0], acc[mt][nt][1]);
                if (r1 < NN)
                    *(__half2*)&g_xh[(size_t)r1 * HCP + col] =
                        __floats2half2_rn(acc[mt][nt][2], acc[mt][nt][3]);
            } else {
                const int h0 = col - HCP, h1 = h0 + 1;
                if (r0 < NN) {
                    if (h0 < H) g_aldst[r0 * H + h0] = acc[mt][nt][0];
                    if (h1 < H) g_aldst[r0 * H + h1] = acc[mt][nt][1];
                }
                if (r1 < NN) {
                    if (h0 < H) g_aldst[r1 * H + h0] = acc[mt][nt][2];
                    if (h1 < H) g_aldst[r1 * H + h1] = acc[mt][nt][3];
                }
            }
        }
    }
}

// ---------------- fused node pass: softmax + max agg + head reduce -------------
// 32 nodes/block, 14 threads/node; chunk-of-4 loads; scalar weight path.
template<int MODE>
__global__ __launch_bounds__(448, 3) void k_node(const float* __restrict__ b,
                                                 float* __restrict__ out) {
    __shared__ float sm[32][H][CP];          // 14 KB
    const int tid = threadIdx.x;             // 448 = 32 nodes * 14 heads
    const int ln = tid / H;
    const int h  = tid % H;
    const int n  = blockIdx.x * 32 + ln;

    if (n < NN) {
        const int cnt = g_cnt[n];
        const int base = n << 6;
        const float ad = g_aldst[n * H + h];
        float den = 0.0f;
        const __half2 NEG2 = __float2half2_rn(-INFINITY);
        __half2 ah0 = NEG2, ah1 = NEG2, ah2 = NEG2, ah3 = NEG2;

        for (int j0 = 0; j0 < cnt; j0 += 4) {
            const int4 q = *(const int4*)&g_bucket[base + j0];
            const int m = cnt - j0;
            int ss[4] = {q.x, q.y, q.z, q.w};
            uint4 u[4];
#pragma unroll
            for (int k = 0; k < 4; k++)
                if (k < m) u[k] = *(const uint4*)&g_xh[(size_t)ss[k] * HCP + h * CP];
#pragma unroll
            for (int k = 0; k < 4; k++) {
                if (k < m) {
                    const __half2* hp = (const __half2*)&u[k];
                    const float als = __half2float(__high2half(hp[3]));
                    const float l = lrelu(als + ad);
                    const float w = __expf(l);
                    den += w;
                    const __half2 w2 = __float2half2_rn(w);
                    ah0 = __hmax2(ah0, __hmul2(w2, hp[0]));
                    ah1 = __hmax2(ah1, __hmul2(w2, hp[1]));
                    ah2 = __hmax2(ah2, __hmul2(w2, hp[2]));
                    ah3 = __hmax2(ah3, __hmul2(w2, hp[3]));  // .y garbage, discarded
                }
            }
        }
        const float inv = 1.0f / den;        // den > 0 (self loop => deg >= 1)
        const float2 F0 = __half22float2(ah0);
        const float2 F1 = __half22float2(ah1);
        const float2 F2 = __half22float2(ah2);
        const float2 F3 = __half22float2(ah3);
        sm[ln][h][0] = F0.x * inv;
        sm[ln][h][1] = F0.y * inv;
        sm[ln][h][2] = F1.x * inv;
        sm[ln][h][3] = F1.y * inv;
        sm[ln][h][4] = F2.x * inv;
        sm[ln][h][5] = F2.y * inv;
        sm[ln][h][6] = F3.x * inv;
    }
    __syncthreads();

    if (MODE == 0) {
        if (tid < 32 * C) {
            const int l2 = tid / C, c = tid % C;
            const int nn = blockIdx.x * 32 + l2;
            if (nn < NN) {
                float s = 0.0f;
#pragma unroll
                for (int hh = 0; hh < H; hh++) s += sm[l2][hh][c];
                out[nn * C + c] = fmaxf(s * (1.0f / H) + b[c], 0.0f);
            }
        }
    } else {
        if (tid < 32) {
            const int nn = blockIdx.x * 32 + tid;
            if (nn < NN) {
                float v[C];
#pragma unroll
                for (int c = 0; c < C; c++) {
                    float s = 0.0f;
#pragma unroll
                    for (int hh = 0; hh < H; hh++) s += sm[tid][hh][c];
                    v[c] = s * (1.0f / H) + b[c];
                }
                float mx = v[0];
#pragma unroll
                for (int c = 1; c < C; c++) mx = fmaxf(mx, v[c]);
                float se = 0.0f;
#pragma unroll
                for (int c = 0; c < C; c++) se += __expf(v[c] - mx);
                const float lse = mx + logf(se);
#pragma unroll
                for (int c = 0; c < C; c++) out[nn * C + c] = v[c] - lse;
            }
        }
    }
}

// ---------------- fused GEMM2 + attention logits (layer 2) ---------------------
__global__ __launch_bounds__(256) void k_gemm2al(const float* __restrict__ W2,
                                                 const float* __restrict__ a_src,
                                                 const float* __restrict__ a_dst) {
    __shared__ float W2s[C][HC];   // 7 x 98
    __shared__ float As[HC], Ad[HC];
    const int tid = threadIdx.x;
    for (int i = tid; i < C * HC; i += 256) W2s[i / HC][i % HC] = W2[i];
    for (int i = tid; i < HC; i += 256) { As[i] = a_src[i]; Ad[i] = a_dst[i]; }
    __syncthreads();

    const int i = blockIdx.x * 256 + tid;
    if (i >= NN * H) return;
    const int n = i / H, h = i % H;
    float hv[C];
#pragma unroll
    for (int k = 0; k < C; k++) hv[k] = g_h[n * C + k];
    float o[C];
    float s1 = 0.0f, s2 = 0.0f;
#pragma unroll
    for (int c = 0; c < C; c++) {
        float s = 0.0f;
#pragma unroll
        for (int k = 0; k < C; k++) s = fmaf(hv[k], W2s[k][h * C + c], s);
        o[c] = s;
        s1 = fmaf(s, As[h * C + c], s1);
        s2 = fmaf(s, Ad[h * C + c], s2);
    }
    g_aldst[i] = s2;
    uint4 u;
    __half2* hp = (__half2*)&u;
    hp[0] = __floats2half2_rn(o[0], o[1]);
    hp[1] = __floats2half2_rn(o[2], o[3]);
    hp[2] = __floats2half2_rn(o[4], o[5]);
    hp[3] = __floats2half2_rn(o[6], s1);   // pack alsrc into pad slot
    *(uint4*)&g_xh[(size_t)n * HCP + h * CP] = u;
}

extern "C" void kernel_launch(void* const* d_in, const int* in_sizes, int n_in,
                              void* d_out, int out_size) {
    const float* x      = (const float*)d_in[0];
    const int*   ei     = (const int*)  d_in[1];
    const float* W1     = (const float*)d_in[2];
    const float* a_src1 = (const float*)d_in[3];
    const float* a_dst1 = (const float*)d_in[4];
    const float* b1     = (const float*)d_in[5];
    const float* W2     = (const float*)d_in[6];
    const float* a_src2 = (const float*)d_in[7];
    const float* a_dst2 = (const float*)d_in[8];
    const float* b2     = (const float*)d_in[9];
    float* out = (float*)d_out;

    const int EB = (ET + 255) / 256;
    const int NB = (NN + 31) / 32;

    float* g_h_ptr;
    cudaGetSymbolAddress((void**)&g_h_ptr, g_h);

    // ----- prep + bucket CSR -----
    k_prep   <<<(FIN * BN + 255) / 256, 256>>>(W1, a_src1, a_dst1);
    k_zero   <<<(NN + 255) / 256, 256>>>();
    k_scatter<<<EB, 256>>>(ei);

    // ----- layer 1 -----
    k_gemm1  <<<(NN + 127) / 128, 256>>>(x);
    k_node<0><<<NB, 448>>>(b1, g_h_ptr);

    // ----- layer 2 -----
    k_gemm2al<<<(NN * H + 255) / 256, 256>>>(W2, a_src2, a_dst2);
    k_node<1><<<NB, 448>>>(b2, out);
}

// round 15
// speedup vs baseline: 1.0922x; 1.0339x over previous
#include <cuda_runtime.h>
#include <cuda_fp16.h>
#include <cstdint>
#include <math.h>

#define NN 100000
#define EE 1600000
#define ET 1700000      // edges + self loops
#define H 14
#define C 7
#define HC 98
#define CP 8            // padded channels (slot 7 carries alsrc fp16)
#define HCP 112         // H * CP
#define FIN 256
#define BN 128          // GEMM1 N: 112 packed xh + 14 aldst + 2 unused
#define CAP 64          // bucket capacity per node (P(deg>63) ~ 1e-16)

#define ASTRIDE 12      // A smem row stride in b32 (conflict-free)
#define BSTRIDE 10      // B smem row stride in b32 (conflict-free)

// ---------------- scratch (device globals; reused across both layers) ----------
__device__ __align__(16) __half g_xh[NN * HCP]; // [N,H,8] fp16; ch7 = alsrc
__device__ float g_aldst[NN * H];    // per-node dst logits
__device__ float g_h[NN * C];        // layer-1 output features
__device__ int g_cnt[NN];            // in-degree (filled by scatter)
__device__ __align__(16) int g_bucket[NN * CAP]; // per-destination source lists
__device__ __align__(16) __half g_Bext[BN * FIN]; // extended B, n-major fp16

__device__ __forceinline__ float lrelu(float v) {
    return v > 0.0f ? v : 0.2f * v;
}

__device__ __forceinline__ unsigned int f2h2(float a, float b) {
    const __half2 h = __floats2half2_rn(a, b);
    return *(const unsigned int*)&h;
}

__device__ __forceinline__ void mma_f16(float* c, const unsigned int* a,
                                        unsigned int b0, unsigned int b1) {
    asm volatile(
        "mma.sync.aligned.m16n8k16.row.col.f32.f16.f16.f32 "
        "{%0,%1,%2,%3},{%4,%5,%6,%7},{%8,%9},{%0,%1,%2,%3};"
        : "+f"(c[0]), "+f"(c[1]), "+f"(c[2]), "+f"(c[3])
        : "r"(a[0]), "r"(a[1]), "r"(a[2]), "r"(a[3]), "r"(b0), "r"(b1));
}

// ---------------- bucket CSR build ---------------------------------------------
__global__ void k_zero() {
    const int i = blockIdx.x * blockDim.x + threadIdx.x;
    if (i < NN) g_cnt[i] = 0;
}

__global__ void k_scatter(const int* __restrict__ ei) {
    const int e = blockIdx.x * blockDim.x + threadIdx.x;
    if (e >= ET) return;
    int s, d;
    if (e < EE) { s = ei[e]; d = ei[EE + e]; } else { s = d = e - EE; }
    const int pos = atomicAdd(&g_cnt[d], 1);
    g_bucket[(d << 6) + pos] = s;
}

// ---------------- build extended B (fp16, n-major): xh + alsrc + aldst cols ----
__global__ void k_prep(const float* __restrict__ W1,
                       const float* __restrict__ a_src,
                       const float* __restrict__ a_dst) {
    const int i = blockIdx.x * blockDim.x + threadIdx.x;  // k*BN + col
    if (i >= FIN * BN) return;
    const int k = i / BN, col = i % BN;
    float v = 0.0f;
    if (col < HCP) {
        const int h = col >> 3, c = col & 7;
        if (c < C) {
            v = W1[k * HC + h * C + c];
        } else {  // alsrc column for head h
            float s = 0.0f;
#pragma unroll
            for (int cc = 0; cc < C; cc++)
                s = fmaf(W1[k * HC + h * C + cc], a_src[h * C + cc], s);
            v = s;
        }
    } else if (col < HCP + H) {  // aldst column for head col-112
        const int h = col - HCP;
        float s = 0.0f;
#pragma unroll
        for (int cc = 0; cc < C; cc++)
            s = fmaf(W1[k * HC + h * C + cc], a_dst[h * C + cc], s);
        v = s;
    }
    g_Bext[col * FIN + k] = __float2half_rn(v);   // n-major (transposed)
}

// ---------------- GEMM1 (FP16 MMA m16n8k16, double-buffered) -------------------
// cols 0..111 -> g_xh fp16 packed (alsrc in ch7); cols 112..125 -> g_aldst fp32
__global__ __launch_bounds__(256) void k_gemm1(const float* __restrict__ x) {
    __shared__ unsigned int As32[2][128 * ASTRIDE];  // fp16x2, 12 b32/row
    __shared__ unsigned int Bs32[2][128 * BSTRIDE];  // fp16x2, 10 b32/row (n-major)
    const int tid = threadIdx.x;
    const int warp = tid >> 5, lane = tid & 31;
    const int gid = lane >> 2, t4 = lane & 3;
    const int wm = warp >> 1, wn = warp & 1;
    const int bm = blockIdx.x * 128;
    const int rb0 = wm * 32;
    const int cb  = wn * 64;

    // A cooperative load: 2 float4 per thread (128 rows x 16 k)
    const int idx0 = tid * 2, idx1 = tid * 2 + 1;
    const int arow0 = idx0 >> 2, akq0 = idx0 & 3;
    const int arow1 = idx1 >> 2, akq1 = idx1 & 3;
    const bool aok0 = (bm + arow0 < NN);
    const bool aok1 = (bm + arow1 < NN);
    // B cooperative load: 4 b32 per thread (128 cols x 8 b32)
    //   b32 index i -> col = i>>3, off = i&7 ; gmem: col*128 + k0/2 + off
    const unsigned int* Bg = (const unsigned int*)g_Bext;

    float acc[2][8][4];
#pragma unroll
    for (int mt = 0; mt < 2; mt++)
#pragma unroll
        for (int nt = 0; nt < 8; nt++)
#pragma unroll
            for (int q = 0; q < 4; q++) acc[mt][nt][q] = 0.0f;

    const float4 Z4 = make_float4(0.f, 0.f, 0.f, 0.f);
    float4 pa0, pa1;
    unsigned int pb[4];

    // prologue: tile 0
    pa0 = aok0 ? *(const float4*)&x[(size_t)(bm + arow0) * FIN + akq0 * 4] : Z4;
    pa1 = aok1 ? *(const float4*)&x[(size_t)(bm + arow1) * FIN + akq1 * 4] : Z4;
#pragma unroll
    for (int j = 0; j < 4; j++) {
        const int i = tid + j * 256;
        pb[j] = Bg[(i >> 3) * 128 + (i & 7)];
    }
    As32[0][arow0 * ASTRIDE + akq0 * 2 + 0] = f2h2(pa0.x, pa0.y);
    As32[0][arow0 * ASTRIDE + akq0 * 2 + 1] = f2h2(pa0.z, pa0.w);
    As32[0][arow1 * ASTRIDE + akq1 * 2 + 0] = f2h2(pa1.x, pa1.y);
    As32[0][arow1 * ASTRIDE + akq1 * 2 + 1] = f2h2(pa1.z, pa1.w);
#pragma unroll
    for (int j = 0; j < 4; j++) {
        const int i = tid + j * 256;
        Bs32[0][(i >> 3) * BSTRIDE + (i & 7)] = pb[j];
    }
    __syncthreads();

#pragma unroll 1
    for (int t = 0; t < 16; t++) {
        const int buf = t & 1;
        // prefetch next tile into registers
        if (t < 15) {
            const int k0 = (t + 1) * 16;
            pa0 = aok0 ? *(const float4*)&x[(size_t)(bm + arow0) * FIN + k0 + akq0 * 4] : Z4;
            pa1 = aok1 ? *(const float4*)&x[(size_t)(bm + arow1) * FIN + k0 + akq1 * 4] : Z4;
#pragma unroll
            for (int j = 0; j < 4; j++) {
                const int i = tid + j * 256;
                pb[j] = Bg[(i >> 3) * 128 + (k0 >> 1) + (i & 7)];
            }
        }
        // one k16 MMA step on current buffer
        {
            unsigned int a[2][4];
#pragma unroll
            for (int mt = 0; mt < 2; mt++) {
                const int r = rb0 + mt * 16 + gid;
                a[mt][0] = As32[buf][r * ASTRIDE + t4];
                a[mt][1] = As32[buf][(r + 8) * ASTRIDE + t4];
                a[mt][2] = As32[buf][r * ASTRIDE + t4 + 4];
                a[mt][3] = As32[buf][(r + 8) * ASTRIDE + t4 + 4];
            }
#pragma unroll
            for (int nt = 0; nt < 8; nt++) {
                const int col = cb + nt * 8 + gid;
                const unsigned int b0 = Bs32[buf][col * BSTRIDE + t4];
                const unsigned int b1 = Bs32[buf][col * BSTRIDE + t4 + 4];
#pragma unroll
                for (int mt = 0; mt < 2; mt++) mma_f16(acc[mt][nt], a[mt], b0, b1);
            }
        }
        // store prefetched tile into the other buffer
        if (t < 15) {
            const int nb = buf ^ 1;
            As32[nb][arow0 * ASTRIDE + akq0 * 2 + 0] = f2h2(pa0.x, pa0.y);
            As32[nb][arow0 * ASTRIDE + akq0 * 2 + 1] = f2h2(pa0.z, pa0.w);
            As32[nb][arow1 * ASTRIDE + akq1 * 2 + 0] = f2h2(pa1.x, pa1.y);
            As32[nb][arow1 * ASTRIDE + akq1 * 2 + 1] = f2h2(pa1.z, pa1.w);
#pragma unroll
            for (int j = 0; j < 4; j++) {
                const int i = tid + j * 256;
                Bs32[nb][(i >> 3) * BSTRIDE + (i & 7)] = pb[j];
            }
        }
        __syncthreads();
    }

    // epilogue: packed fp16 store (cols<112) or fp32 aldst store (cols 112..125)
#pragma unroll
    for (int mt = 0; mt < 2; mt++) {
        const int r0 = bm + rb0 + mt * 16 + gid;
        const int r1 = r0 + 8;
#pragma unroll
        for (int nt = 0; nt < 8; nt++) {
            const int col = cb + nt * 8 + t4 * 2;
            if (col < HCP) {
                if (r0 < NN)
                    *(__half2*)&g_xh[(size_t)r0 * HCP + col] =
                        __floats2half2_rn(acc[mt][nt][0], acc[mt][nt][1]);
                if (r1 < NN)
                    *(__half2*)&g_xh[(size_t)r1 * HCP + col] =
                        __floats2half2_rn(acc[mt][nt][2], acc[mt][nt][3]);
            } else {
                const int h0 = col - HCP, h1 = h0 + 1;
                if (r0 < NN) {
                    if (h0 < H) g_aldst[r0 * H + h0] = acc[mt][nt][0];
                    if (h1 < H) g_aldst[r0 * H + h1] = acc[mt][nt][1];
                }
                if (r1 < NN) {
                    if (h0 < H) g_aldst[r1 * H + h0] = acc[mt][nt][2];
                    if (h1 < H) g_aldst[r1 * H + h1] = acc[mt][nt][3];
                }
            }
        }
    }
}

// ---------------- fused node pass: softmax + max agg + head reduce -------------
// 32 nodes/block, 14 threads/node; chunk-of-4 loads; scalar weight path.
template<int MODE>
__global__ __launch_bounds__(448, 3) void k_node(const float* __restrict__ b,
                                                 float* __restrict__ out) {
    __shared__ float sm[32][H][CP];          // 14 KB
    const int tid = threadIdx.x;             // 448 = 32 nodes * 14 heads
    const int ln = tid / H;
    const int h  = tid % H;
    const int n  = blockIdx.x * 32 + ln;

    if (n < NN) {
        const int cnt = g_cnt[n];
        const int base = n << 6;
        const float ad = g_aldst[n * H + h];
        float den = 0.0f;
        const __half2 NEG2 = __float2half2_rn(-INFINITY);
        __half2 ah0 = NEG2, ah1 = NEG2, ah2 = NEG2, ah3 = NEG2;

        for (int j0 = 0; j0 < cnt; j0 += 4) {
            const int4 q = *(const int4*)&g_bucket[base + j0];
            const int m = cnt - j0;
            int ss[4] = {q.x, q.y, q.z, q.w};
            uint4 u[4];
#pragma unroll
            for (int k = 0; k < 4; k++)
                if (k < m) u[k] = *(const uint4*)&g_xh[(size_t)ss[k] * HCP + h * CP];
#pragma unroll
            for (int k = 0; k < 4; k++) {
                if (k < m) {
                    const __half2* hp = (const __half2*)&u[k];
                    const float als = __half2float(__high2half(hp[3]));
                    const float l = lrelu(als + ad);
                    const float w = __expf(l);
                    den += w;
                    const __half2 w2 = __float2half2_rn(w);
                    ah0 = __hmax2(ah0, __hmul2(w2, hp[0]));
                    ah1 = __hmax2(ah1, __hmul2(w2, hp[1]));
                    ah2 = __hmax2(ah2, __hmul2(w2, hp[2]));
                    ah3 = __hmax2(ah3, __hmul2(w2, hp[3]));  // .y garbage, discarded
                }
            }
        }
        const float inv = 1.0f / den;        // den > 0 (self loop => deg >= 1)
        const float2 F0 = __half22float2(ah0);
        const float2 F1 = __half22float2(ah1);
        const float2 F2 = __half22float2(ah2);
        const float2 F3 = __half22float2(ah3);
        sm[ln][h][0] = F0.x * inv;
        sm[ln][h][1] = F0.y * inv;
        sm[ln][h][2] = F1.x * inv;
        sm[ln][h][3] = F1.y * inv;
        sm[ln][h][4] = F2.x * inv;
        sm[ln][h][5] = F2.y * inv;
        sm[ln][h][6] = F3.x * inv;
    }
    __syncthreads();

    if (MODE == 0) {
        if (tid < 32 * C) {
            const int l2 = tid / C, c = tid % C;
            const int nn = blockIdx.x * 32 + l2;
            if (nn < NN) {
                float s = 0.0f;
#pragma unroll
                for (int hh = 0; hh < H; hh++) s += sm[l2][hh][c];
                out[nn * C + c] = fmaxf(s * (1.0f / H) + b[c], 0.0f);
            }
        }
    } else {
        if (tid < 32) {
            const int nn = blockIdx.x * 32 + tid;
            if (nn < NN) {
                float v[C];
#pragma unroll
                for (int c = 0; c < C; c++) {
                    float s = 0.0f;
#pragma unroll
                    for (int hh = 0; hh < H; hh++) s += sm[tid][hh][c];
                    v[c] = s * (1.0f / H) + b[c];
                }
                float mx = v[0];
#pragma unroll
                for (int c = 1; c < C; c++) mx = fmaxf(mx, v[c]);
                float se = 0.0f;
#pragma unroll
                for (int c = 0; c < C; c++) se += __expf(v[c] - mx);
                const float lse = mx + logf(se);
#pragma unroll
                for (int c = 0; c < C; c++) out[nn * C + c] = v[c] - lse;
            }
        }
    }
}

// ---------------- fused GEMM2 + attention logits (layer 2) ---------------------
__global__ __launch_bounds__(256) void k_gemm2al(const float* __restrict__ W2,
                                                 const float* __restrict__ a_src,
                                                 const float* __restrict__ a_dst) {
    __shared__ float W2s[C][HC];   // 7 x 98
    __shared__ float As[HC], Ad[HC];
    const int tid = threadIdx.x;
    for (int i = tid; i < C * HC; i += 256) W2s[i / HC][i % HC] = W2[i];
    for (int i = tid; i < HC; i += 256) { As[i] = a_src[i]; Ad[i] = a_dst[i]; }
    __syncthreads();

    const int i = blockIdx.x * 256 + tid;
    if (i >= NN * H) return;
    const int n = i / H, h = i % H;
    float hv[C];
#pragma unroll
    for (int k = 0; k < C; k++) hv[k] = g_h[n * C + k];
    float o[C];
    float s1 = 0.0f, s2 = 0.0f;
#pragma unroll
    for (int c = 0; c < C; c++) {
        float s = 0.0f;
#pragma unroll
        for (int k = 0; k < C; k++) s = fmaf(hv[k], W2s[k][h * C + c], s);
        o[c] = s;
        s1 = fmaf(s, As[h * C + c], s1);
        s2 = fmaf(s, Ad[h * C + c], s2);
    }
    g_aldst[i] = s2;
    uint4 u;
    __half2* hp = (__half2*)&u;
    hp[0] = __floats2half2_rn(o[0], o[1]);
    hp[1] = __floats2half2_rn(o[2], o[3]);
    hp[2] = __floats2half2_rn(o[4], o[5]);
    hp[3] = __floats2half2_rn(o[6], s1);   // pack alsrc into pad slot
    *(uint4*)&g_xh[(size_t)n * HCP + h * CP] = u;
}

extern "C" void kernel_launch(void* const* d_in, const int* in_sizes, int n_in,
                              void* d_out, int out_size) {
    const float* x      = (const float*)d_in[0];
    const int*   ei     = (const int*)  d_in[1];
    const float* W1     = (const float*)d_in[2];
    const float* a_src1 = (const float*)d_in[3];
    const float* a_dst1 = (const float*)d_in[4];
    const float* b1     = (const float*)d_in[5];
    const float* W2     = (const float*)d_in[6];
    const float* a_src2 = (const float*)d_in[7];
    const float* a_dst2 = (const float*)d_in[8];
    const float* b2     = (const float*)d_in[9];
    float* out = (float*)d_out;

    const int EB = (ET + 255) / 256;
    const int NB = (NN + 31) / 32;

    float* g_h_ptr;
    cudaGetSymbolAddress((void**)&g_h_ptr, g_h);

    // ----- prep + bucket CSR -----
    k_prep   <<<(FIN * BN + 255) / 256, 256>>>(W1, a_src1, a_dst1);
    k_zero   <<<(NN + 255) / 256, 256>>>();
    k_scatter<<<EB, 256>>>(ei);

    // ----- layer 1 -----
    k_gemm1  <<<(NN + 127) / 128, 256>>>(x);
    k_node<0><<<NB, 448>>>(b1, g_h_ptr);

    // ----- layer 2 -----
    k_gemm2al<<<(NN * H + 255) / 256, 256>>>(W2, a_src2, a_dst2);
    k_node<1><<<NB, 448>>>(b2, out);
}

// round 16
// speedup vs baseline: 1.1482x; 1.0512x over previous
#include <cuda_runtime.h>
#include <cuda_fp16.h>
#include <cstdint>
#include <math.h>

#define NN 100000
#define EE 1600000
#define ET 1700000      // edges + self loops
#define H 14
#define C 7
#define HC 98
#define CP 8            // padded channels (slot 7 carries alsrc fp16)
#define HCP 112         // H * CP
#define FIN 256
#define BN 128          // GEMM1 N: 112 packed xh + 14 aldst + 2 unused
#define CAP 64          // bucket capacity per node (P(deg>63) ~ 1e-16)

#define TSTRIDE 12      // smem row stride in b32 (48B; conflict-free for ldmatrix)
#define BUFB32 (128 * TSTRIDE)      // b32 per buffer
#define BUFBYTES (BUFB32 * 4)       // 6144 bytes

// ---------------- scratch (device globals; reused across both layers) ----------
__device__ __align__(16) __half g_xh[NN * HCP]; // [N,H,8] fp16; ch7 = alsrc
__device__ float g_aldst[NN * H];    // per-node dst logits
__device__ float g_h[NN * C];        // layer-1 output features
__device__ int g_cnt[NN];            // in-degree (filled by scatter)
__device__ __align__(16) int g_bucket[NN * CAP]; // per-destination source lists
__device__ __align__(16) __half g_Bext[BN * FIN]; // extended B, n-major fp16

__device__ __forceinline__ float lrelu(float v) {
    return v > 0.0f ? v : 0.2f * v;
}

__device__ __forceinline__ unsigned int f2h2(float a, float b) {
    const __half2 h = __floats2half2_rn(a, b);
    return *(const unsigned int*)&h;
}

__device__ __forceinline__ void mma_f16(float* c, const unsigned int* a,
                                        unsigned int b0, unsigned int b1) {
    asm volatile(
        "mma.sync.aligned.m16n8k16.row.col.f32.f16.f16.f32 "
        "{%0,%1,%2,%3},{%4,%5,%6,%7},{%8,%9},{%0,%1,%2,%3};"
        : "+f"(c[0]), "+f"(c[1]), "+f"(c[2]), "+f"(c[3])
        : "r"(a[0]), "r"(a[1]), "r"(a[2]), "r"(a[3]), "r"(b0), "r"(b1));
}

__device__ __forceinline__ void ldsm_x4(unsigned int& r0, unsigned int& r1,
                                        unsigned int& r2, unsigned int& r3,
                                        unsigned int addr) {
    asm volatile(
        "ldmatrix.sync.aligned.m8n8.x4.shared.b16 {%0,%1,%2,%3}, [%4];"
        : "=r"(r0), "=r"(r1), "=r"(r2), "=r"(r3) : "r"(addr));
}

// ---------------- bucket CSR build ---------------------------------------------
__global__ void k_zero() {
    const int i = blockIdx.x * blockDim.x + threadIdx.x;
    if (i < NN) g_cnt[i] = 0;
}

__global__ void k_scatter(const int* __restrict__ ei) {
    const int e = blockIdx.x * blockDim.x + threadIdx.x;
    if (e >= ET) return;
    int s, d;
    if (e < EE) { s = ei[e]; d = ei[EE + e]; } else { s = d = e - EE; }
    const int pos = atomicAdd(&g_cnt[d], 1);
    g_bucket[(d << 6) + pos] = s;
}

// ---------------- build extended B (fp16, n-major): xh + alsrc + aldst cols ----
__global__ void k_prep(const float* __restrict__ W1,
                       const float* __restrict__ a_src,
                       const float* __restrict__ a_dst) {
    const int i = blockIdx.x * blockDim.x + threadIdx.x;  // k*BN + col
    if (i >= FIN * BN) return;
    const int k = i / BN, col = i % BN;
    float v = 0.0f;
    if (col < HCP) {
        const int h = col >> 3, c = col & 7;
        if (c < C) {
            v = W1[k * HC + h * C + c];
        } else {  // alsrc column for head h
            float s = 0.0f;
#pragma unroll
            for (int cc = 0; cc < C; cc++)
                s = fmaf(W1[k * HC + h * C + cc], a_src[h * C + cc], s);
            v = s;
        }
    } else if (col < HCP + H) {  // aldst column for head col-112
        const int h = col - HCP;
        float s = 0.0f;
#pragma unroll
        for (int cc = 0; cc < C; cc++)
            s = fmaf(W1[k * HC + h * C + cc], a_dst[h * C + cc], s);
        v = s;
    }
    g_Bext[col * FIN + k] = __float2half_rn(v);   // n-major (transposed)
}

// ---------------- GEMM1 (FP16 MMA m16n8k16 + ldmatrix, double-buffered) --------
// cols 0..111 -> g_xh fp16 packed (alsrc in ch7); cols 112..125 -> g_aldst fp32
__global__ __launch_bounds__(256) void k_gemm1(const float* __restrict__ x) {
    __shared__ unsigned int As32[2][BUFB32];  // fp16x2, 12 b32/row
    __shared__ unsigned int Bs32[2][BUFB32];  // fp16x2, 12 b32/row (n-major)
    const int tid = threadIdx.x;
    const int warp = tid >> 5, lane = tid & 31;
    const int gid = lane >> 2, t4 = lane & 3;
    const int wm = warp >> 1, wn = warp & 1;
    const int bm = blockIdx.x * 128;
    const int rb0 = wm * 32;
    const int cb  = wn * 64;

    // A cooperative load: 2 float4 per thread (128 rows x 16 k)
    const int idx0 = tid * 2, idx1 = tid * 2 + 1;
    const int arow0 = idx0 >> 2, akq0 = idx0 & 3;
    const int arow1 = idx1 >> 2, akq1 = idx1 & 3;
    const bool aok0 = (bm + arow0 < NN);
    const bool aok1 = (bm + arow1 < NN);
    const unsigned int* Bg = (const unsigned int*)g_Bext;

    // ldmatrix lane addresses (bytes, relative to buffer 0)
    const unsigned int a_base = (unsigned int)__cvta_generic_to_shared(&As32[0][0]);
    const unsigned int b_base = (unsigned int)__cvta_generic_to_shared(&Bs32[0][0]);
    const unsigned int a_addr0 = a_base + (rb0 + (lane & 15)) * 48 + (lane >> 4) * 16;
    const unsigned int a_addr1 = a_addr0 + 16 * 48;
    unsigned int b_addr[4];
#pragma unroll
    for (int p = 0; p < 4; p++)
        b_addr[p] = b_base + (cb + p * 16 + ((lane >> 4) & 1) * 8 + (lane & 7)) * 48
                  + ((lane >> 3) & 1) * 16;

    float acc[2][8][4];
#pragma unroll
    for (int mt = 0; mt < 2; mt++)
#pragma unroll
        for (int nt = 0; nt < 8; nt++)
#pragma unroll
            for (int q = 0; q < 4; q++) acc[mt][nt][q] = 0.0f;

    const float4 Z4 = make_float4(0.f, 0.f, 0.f, 0.f);
    float4 pa0, pa1;
    unsigned int pb[4];

    // prologue: tile 0
    pa0 = aok0 ? *(const float4*)&x[(size_t)(bm + arow0) * FIN + akq0 * 4] : Z4;
    pa1 = aok1 ? *(const float4*)&x[(size_t)(bm + arow1) * FIN + akq1 * 4] : Z4;
#pragma unroll
    for (int j = 0; j < 4; j++) {
        const int i = tid + j * 256;
        pb[j] = Bg[(i >> 3) * 128 + (i & 7)];
    }
    As32[0][arow0 * TSTRIDE + akq0 * 2 + 0] = f2h2(pa0.x, pa0.y);
    As32[0][arow0 * TSTRIDE + akq0 * 2 + 1] = f2h2(pa0.z, pa0.w);
    As32[0][arow1 * TSTRIDE + akq1 * 2 + 0] = f2h2(pa1.x, pa1.y);
    As32[0][arow1 * TSTRIDE + akq1 * 2 + 1] = f2h2(pa1.z, pa1.w);
#pragma unroll
    for (int j = 0; j < 4; j++) {
        const int i = tid + j * 256;
        Bs32[0][(i >> 3) * TSTRIDE + (i & 7)] = pb[j];
    }
    __syncthreads();

#pragma unroll 1
    for (int t = 0; t < 16; t++) {
        const unsigned int boff = (t & 1) ? BUFBYTES : 0;
        // prefetch next tile into registers
        if (t < 15) {
            const int k0 = (t + 1) * 16;
            pa0 = aok0 ? *(const float4*)&x[(size_t)(bm + arow0) * FIN + k0 + akq0 * 4] : Z4;
            pa1 = aok1 ? *(const float4*)&x[(size_t)(bm + arow1) * FIN + k0 + akq1 * 4] : Z4;
#pragma unroll
            for (int j = 0; j < 4; j++) {
                const int i = tid + j * 256;
                pb[j] = Bg[(i >> 3) * 128 + (k0 >> 1) + (i & 7)];
            }
        }
        // one k16 MMA step on current buffer: 2 A-LDSM + 4 B-LDSM + 16 MMA
        {
            unsigned int a[2][4], bf[4][4];
            ldsm_x4(a[0][0], a[0][1], a[0][2], a[0][3], a_addr0 + boff);
            ldsm_x4(a[1][0], a[1][1], a[1][2], a[1][3], a_addr1 + boff);
#pragma unroll
            for (int p = 0; p < 4; p++)
                ldsm_x4(bf[p][0], bf[p][1], bf[p][2], bf[p][3], b_addr[p] + boff);
#pragma unroll
            for (int nt = 0; nt < 8; nt++) {
                const unsigned int b0 = bf[nt >> 1][(nt & 1) * 2 + 0];
                const unsigned int b1 = bf[nt >> 1][(nt & 1) * 2 + 1];
#pragma unroll
                for (int mt = 0; mt < 2; mt++) mma_f16(acc[mt][nt], a[mt], b0, b1);
            }
        }
        // store prefetched tile into the other buffer
        if (t < 15) {
            const int nb = (t & 1) ^ 1;
            As32[nb][arow0 * TSTRIDE + akq0 * 2 + 0] = f2h2(pa0.x, pa0.y);
            As32[nb][arow0 * TSTRIDE + akq0 * 2 + 1] = f2h2(pa0.z, pa0.w);
            As32[nb][arow1 * TSTRIDE + akq1 * 2 + 0] = f2h2(pa1.x, pa1.y);
            As32[nb][arow1 * TSTRIDE + akq1 * 2 + 1] = f2h2(pa1.z, pa1.w);
#pragma unroll
            for (int j = 0; j < 4; j++) {
                const int i = tid + j * 256;
                Bs32[nb][(i >> 3) * TSTRIDE + (i & 7)] = pb[j];
            }
        }
        __syncthreads();
    }

    // epilogue: packed fp16 store (cols<112) or fp32 aldst store (cols 112..125)
#pragma unroll
    for (int mt = 0; mt < 2; mt++) {
        const int r0 = bm + rb0 + mt * 16 + gid;
        const int r1 = r0 + 8;
#pragma unroll
        for (int nt = 0; nt < 8; nt++) {
            const int col = cb + nt * 8 + t4 * 2;
            if (col < HCP) {
                if (r0 < NN)
                    *(__half2*)&g_xh[(size_t)r0 * HCP + col] =
                        __floats2half2_rn(acc[mt][nt][0], acc[mt][nt][1]);
                if (r1 < NN)
                    *(__half2*)&g_xh[(size_t)r1 * HCP + col] =
                        __floats2half2_rn(acc[mt][nt][2], acc[mt][nt][3]);
            } else {
                const int h0 = col - HCP, h1 = h0 + 1;
                if (r0 < NN) {
                    if (h0 < H) g_aldst[r0 * H + h0] = acc[mt][nt][0];
                    if (h1 < H) g_aldst[r0 * H + h1] = acc[mt][nt][1];
                }
                if (r1 < NN) {
                    if (h0 < H) g_aldst[r1 * H + h0] = acc[mt][nt][2];
                    if (h1 < H) g_aldst[r1 * H + h1] = acc[mt][nt][3];
                }
            }
        }
    }
}

// ---------------- fused node pass: softmax + max agg + head reduce -------------
// 32 nodes/block, 14 threads/node; chunk-of-4 loads; scalar weight path.
template<int MODE>
__global__ __launch_bounds__(448, 3) void k_node(const float* __restrict__ b,
                                                 float* __restrict__ out) {
    __shared__ float sm[32][H][CP];          // 14 KB
    const int tid = threadIdx.x;             // 448 = 32 nodes * 14 heads
    const int ln = tid / H;
    const int h  = tid % H;
    const int n  = blockIdx.x * 32 + ln;

    if (n < NN) {
        const int cnt = g_cnt[n];
        const int base = n << 6;
        const float ad = g_aldst[n * H + h];
        float den = 0.0f;
        const __half2 NEG2 = __float2half2_rn(-INFINITY);
        __half2 ah0 = NEG2, ah1 = NEG2, ah2 = NEG2, ah3 = NEG2;

        for (int j0 = 0; j0 < cnt; j0 += 4) {
            const int4 q = *(const int4*)&g_bucket[base + j0];
            const int m = cnt - j0;
            int ss[4] = {q.x, q.y, q.z, q.w};
            uint4 u[4];
#pragma unroll
            for (int k = 0; k < 4; k++)
                if (k < m) u[k] = *(const uint4*)&g_xh[(size_t)ss[k] * HCP + h * CP];
#pragma unroll
            for (int k = 0; k < 4; k++) {
                if (k < m) {
                    const __half2* hp = (const __half2*)&u[k];
                    const float als = __half2float(__high2half(hp[3]));
                    const float l = lrelu(als + ad);
                    const float w = __expf(l);
                    den += w;
                    const __half2 w2 = __float2half2_rn(w);
                    ah0 = __hmax2(ah0, __hmul2(w2, hp[0]));
                    ah1 = __hmax2(ah1, __hmul2(w2, hp[1]));
                    ah2 = __hmax2(ah2, __hmul2(w2, hp[2]));
                    ah3 = __hmax2(ah3, __hmul2(w2, hp[3]));  // .y garbage, discarded
                }
            }
        }
        const float inv = 1.0f / den;        // den > 0 (self loop => deg >= 1)
        const float2 F0 = __half22float2(ah0);
        const float2 F1 = __half22float2(ah1);
        const float2 F2 = __half22float2(ah2);
        const float2 F3 = __half22float2(ah3);
        sm[ln][h][0] = F0.x * inv;
        sm[ln][h][1] = F0.y * inv;
        sm[ln][h][2] = F1.x * inv;
        sm[ln][h][3] = F1.y * inv;
        sm[ln][h][4] = F2.x * inv;
        sm[ln][h][5] = F2.y * inv;
        sm[ln][h][6] = F3.x * inv;
    }
    __syncthreads();

    if (MODE == 0) {
        if (tid < 32 * C) {
            const int l2 = tid / C, c = tid % C;
            const int nn = blockIdx.x * 32 + l2;
            if (nn < NN) {
                float s = 0.0f;
#pragma unroll
                for (int hh = 0; hh < H; hh++) s += sm[l2][hh][c];
                out[nn * C + c] = fmaxf(s * (1.0f / H) + b[c], 0.0f);
            }
        }
    } else {
        if (tid < 32) {
            const int nn = blockIdx.x * 32 + tid;
            if (nn < NN) {
                float v[C];
#pragma unroll
                for (int c = 0; c < C; c++) {
                    float s = 0.0f;
#pragma unroll
                    for (int hh = 0; hh < H; hh++) s += sm[tid][hh][c];
                    v[c] = s * (1.0f / H) + b[c];
                }
                float mx = v[0];
#pragma unroll
                for (int c = 1; c < C; c++) mx = fmaxf(mx, v[c]);
                float se = 0.0f;
#pragma unroll
                for (int c = 0; c < C; c++) se += __expf(v[c] - mx);
                const float lse = mx + logf(se);
#pragma unroll
                for (int c = 0; c < C; c++) out[nn * C + c] = v[c] - lse;
            }
        }
    }
}

// ---------------- fused GEMM2 + attention logits (layer 2) ---------------------
__global__ __launch_bounds__(256) void k_gemm2al(const float* __restrict__ W2,
                                                 const float* __restrict__ a_src,
                                                 const float* __restrict__ a_dst) {
    __shared__ float W2s[C][HC];   // 7 x 98
    __shared__ float As[HC], Ad[HC];
    const int tid = threadIdx.x;
    for (int i = tid; i < C * HC; i += 256) W2s[i / HC][i % HC] = W2[i];
    for (int i = tid; i < HC; i += 256) { As[i] = a_src[i]; Ad[i] = a_dst[i]; }
    __syncthreads();

    const int i = blockIdx.x * 256 + tid;
    if (i >= NN * H) return;
    const int n = i / H, h = i % H;
    float hv[C];
#pragma unroll
    for (int k = 0; k < C; k++) hv[k] = g_h[n * C + k];
    float o[C];
    float s1 = 0.0f, s2 = 0.0f;
#pragma unroll
    for (int c = 0; c < C; c++) {
        float s = 0.0f;
#pragma unroll
        for (int k = 0; k < C; k++) s = fmaf(hv[k], W2s[k][h * C + c], s);
        o[c] = s;
        s1 = fmaf(s, As[h * C + c], s1);
        s2 = fmaf(s, Ad[h * C + c], s2);
    }
    g_aldst[i] = s2;
    uint4 u;
    __half2* hp = (__half2*)&u;
    hp[0] = __floats2half2_rn(o[0], o[1]);
    hp[1] = __floats2half2_rn(o[2], o[3]);
    hp[2] = __floats2half2_rn(o[4], o[5]);
    hp[3] = __floats2half2_rn(o[6], s1);   // pack alsrc into pad slot
    *(uint4*)&g_xh[(size_t)n * HCP + h * CP] = u;
}

extern "C" void kernel_launch(void* const* d_in, const int* in_sizes, int n_in,
                              void* d_out, int out_size) {
    const float* x      = (const float*)d_in[0];
    const int*   ei     = (const int*)  d_in[1];
    const float* W1     = (const float*)d_in[2];
    const float* a_src1 = (const float*)d_in[3];
    const float* a_dst1 = (const float*)d_in[4];
    const float* b1     = (const float*)d_in[5];
    const float* W2     = (const float*)d_in[6];
    const float* a_src2 = (const float*)d_in[7];
    const float* a_dst2 = (const float*)d_in[8];
    const float* b2     = (const float*)d_in[9];
    float* out = (float*)d_out;

    const int EB = (ET + 255) / 256;
    const int NB = (NN + 31) / 32;

    float* g_h_ptr;
    cudaGetSymbolAddress((void**)&g_h_ptr, g_h);

    // ----- prep + bucket CSR -----
    k_prep   <<<(FIN * BN + 255) / 256, 256>>>(W1, a_src1, a_dst1);
    k_zero   <<<(NN + 255) / 256, 256>>>();
    k_scatter<<<EB, 256>>>(ei);

    // ----- layer 1 -----
    k_gemm1  <<<(NN + 127) / 128, 256>>>(x);
    k_node<0><<<NB, 448>>>(b1, g_h_ptr);

    // ----- layer 2 -----
    k_gemm2al<<<(NN * H + 255) / 256, 256>>>(W2, a_src2, a_dst2);
    k_node<1><<<NB, 448>>>(b2, out);
}